// round 1
// baseline (speedup 1.0000x reference)
#include <cuda_runtime.h>
#include <math.h>
#include <float.h>

// Problem constants (match reference)
#define Bn 128
#define Tn 64
#define Cn 6625
#define Ln 25
#define Kn 6
#define Sn (2*Ln + 1)          // 51
#define NEGF (-1e30f)
#define ALPHA_C 0.1f
#define TAIL_C 0.01f
#define NSEQ (Bn + Bn*Kn)      // 896 CTC sequences
#define NCAND 128              // beam candidate chars per sample-timestep (64 c1 + 64 c2)

// ---------------- device scratch (static; no runtime alloc) ----------------
__device__ float g_logZ[Bn*Tn];
__device__ float g_m1[Bn*Tn];
__device__ float g_m2[Bn*Tn];
__device__ int   g_i1[Bn*Tn];
__device__ int   g_i2[Bn*Tn];
__device__ float g_lpb0[Bn*Tn];                 // lp of blank per (b,t)
__device__ float g_tbl[Bn*Tn*NCAND];            // lp at candidate chars, 4MB
__device__ float g_conf[Bn];
__device__ float g_nll[NSEQ];

__device__ __forceinline__ float lae(float a, float b) {
    float mx = fmaxf(a, b), mn = fminf(a, b);
    return mx + log1pf(expf(mn - mx));
}

// ---------------- kernel 1: per-(b,t) row stats over C=6625 ----------------
// One block per row; online logsumexp + top-2 (values & indices) over c>=1.
__global__ __launch_bounds__(256) void k_rowstats(const float* __restrict__ preds) {
    int row = blockIdx.x;                       // b*T + t
    const float* p = preds + (long long)row * Cn;
    int tid = threadIdx.x;

    float mx = -FLT_MAX, sm = 0.f;
    float m1 = -FLT_MAX, m2 = -FLT_MAX;
    int   i1 = 0x7fffffff, i2 = 0x7fffffff;

    for (int c = tid; c < Cn; c += 256) {
        float v = __ldg(p + c);
        // online logsumexp
        if (v > mx) { sm = sm * __expf(mx - v) + 1.f; mx = v; }
        else        { sm += __expf(v - mx); }
        // top-2 over non-blank classes
        if (c >= 1) {
            if (v > m1)      { m2 = m1; i2 = i1; m1 = v; i1 = c; }
            else if (v > m2) { m2 = v; i2 = c; }
        }
    }

    __shared__ float s_mx[256], s_sm[256], s_m1[256], s_m2[256];
    __shared__ int   s_i1[256], s_i2[256];
    s_mx[tid]=mx; s_sm[tid]=sm; s_m1[tid]=m1; s_m2[tid]=m2; s_i1[tid]=i1; s_i2[tid]=i2;
    __syncthreads();

    for (int off = 128; off > 0; off >>= 1) {
        if (tid < off) {
            // merge logsumexp
            float mxa = s_mx[tid],      sma = s_sm[tid];
            float mxb = s_mx[tid+off],  smb = s_sm[tid+off];
            if (mxb > mxa) { sma = sma * expf(mxa - mxb) + smb; mxa = mxb; }
            else           { sma = sma + smb * expf(mxb - mxa); }
            s_mx[tid] = mxa; s_sm[tid] = sma;
            // merge top-2 (tie -> smaller index, matching jnp.argmax)
            float a1 = s_m1[tid];     int a1i = s_i1[tid];
            float a2 = s_m2[tid];     int a2i = s_i2[tid];
            float b1 = s_m1[tid+off]; int b1i = s_i1[tid+off];
            float b2 = s_m2[tid+off]; int b2i = s_i2[tid+off];
            if (b1 > a1 || (b1 == a1 && b1i < a1i)) { a2=a1; a2i=a1i; a1=b1; a1i=b1i; }
            else if (b1 > a2 || (b1 == a2 && b1i < a2i)) { a2=b1; a2i=b1i; }
            if (b2 > a1 || (b2 == a1 && b2i < a1i)) { a2=a1; a2i=a1i; a1=b2; a1i=b2i; }
            else if (b2 > a2 || (b2 == a2 && b2i < a2i)) { a2=b2; a2i=b2i; }
            s_m1[tid]=a1; s_i1[tid]=a1i; s_m2[tid]=a2; s_i2[tid]=a2i;
        }
        __syncthreads();
    }
    if (tid == 0) {
        float lz = s_mx[0] + logf(s_sm[0]);
        g_logZ[row] = lz;
        g_m1[row] = s_m1[0]; g_i1[row] = s_i1[0];
        g_m2[row] = s_m2[0]; g_i2[row] = s_i2[0];
        g_lpb0[row] = __ldg(p) - lz;
    }
}

// ---------------- kernel 2: gather beam candidate lp table ----------------
// tbl[(b,t), j] = lp_{b,t}[ c1[b,j] ] for j<64, lp_{b,t}[ c2[b,j-64] ] for j>=64
__global__ __launch_bounds__(NCAND) void k_gather(const float* __restrict__ preds) {
    int row = blockIdx.x;                       // b*T + t
    int j   = threadIdx.x;                      // 0..127
    int b   = row / Tn;
    int ch  = (j < Tn) ? g_i1[b*Tn + j] : g_i2[b*Tn + (j - Tn)];
    g_tbl[(long long)row * NCAND + j] =
        __ldg(preds + (long long)row * Cn + ch) - g_logZ[row];
}

// ---------------- kernel 3: fused beam confidence + CTC alpha ----------------
// blocks [0,Bn): beam-1 prefix search per sample
// blocks [Bn, Bn+NSEQ): CTC forward per sequence (master then smooth)
__global__ __launch_bounds__(128) void k_beam_ctc(
    const float* __restrict__ preds,
    const int* __restrict__ text,
    const int* __restrict__ preds_size,
    const int* __restrict__ length,
    const int* __restrict__ smooth_text,
    const int* __restrict__ smooth_length)
{
    int tid = threadIdx.x;

    if (blockIdx.x < Bn) {
        // ================= beam confidence =================
        int b = blockIdx.x;
        __shared__ float stbl[Tn * NCAND];      // 32KB
        __shared__ float sm1[Tn], sm2[Tn], slz[Tn], slpb[Tn];
        __shared__ int   si1[Tn], si2[Tn];

        const float* gt = g_tbl + (long long)b * Tn * NCAND;
        for (int idx = tid; idx < Tn * NCAND; idx += 128) stbl[idx] = gt[idx];
        if (tid < Tn) {
            int r = b * Tn + tid;
            sm1[tid] = g_m1[r]; sm2[tid] = g_m2[r];
            si1[tid] = g_i1[r]; si2[tid] = g_i2[r];
            slz[tid] = g_logZ[r]; slpb[tid] = g_lpb0[r];
        }
        __syncthreads();

        if (tid == 0) {
            float lpb = 0.f, lpnb = NEGF;
            int last = -1, lastj = 0;
            for (int t = 0; t < Tn; t++) {
                float lp_last = (last >= 0) ? stbl[t * NCAND + lastj] : NEGF;
                float tot    = lae(lpb, lpnb);
                float new_pb = tot + slpb[t];
                float rep    = (last >= 0) ? (lpnb + lp_last) : NEGF;
                float keep   = lae(new_pb, rep);
                float lpm1 = sm1[t] - slz[t];
                float lpm2 = sm2[t] - slz[t];
                float best_ext; int best_c, best_j;
                if (si1[t] != last) {
                    best_ext = tot + lpm1; best_c = si1[t]; best_j = t;
                } else {
                    float cA = lpb + lpm1;          // ext[last] uses lpb
                    float cB = tot + lpm2;          // runner-up class
                    if (cA > cB || (cA == cB && last < si2[t])) {
                        best_ext = cA; best_c = last; best_j = t;
                    } else {
                        best_ext = cB; best_c = si2[t]; best_j = Tn + t;
                    }
                }
                bool take = best_ext > keep;
                lpb   = take ? NEGF     : new_pb;
                lpnb  = take ? best_ext : rep;
                last  = take ? best_c   : last;
                lastj = take ? best_j   : lastj;
            }
            float score = lae(lpb, lpnb);
            g_conf[b] = expf(score / (float)Tn);
        }
        return;
    }

    // ================= CTC forward =================
    int n = blockIdx.x - Bn;                    // 0..NSEQ-1
    int b, tlen, ilen;
    const int* lab;
    if (n < Bn) {
        b = n; lab = text + n * Ln;
        tlen = length[n]; ilen = preds_size[n];
    } else {
        int m = n - Bn;
        b = m / Kn; lab = smooth_text + m * Ln;
        tlen = smooth_length[m]; ilen = Tn;
    }

    __shared__ int   ext[Sn];
    __shared__ int   skipf[Sn];
    __shared__ float bufA[Sn + 2], bufB[Sn + 2];
    __shared__ float slz2[Tn];

    int s = tid;                                // active states: s < Sn
    if (s < Sn) ext[s] = (s & 1) ? lab[(s - 1) >> 1] : 0;
    if (s < 2) { bufA[s] = NEGF; bufB[s] = NEGF; }
    if (s >= 64 && s < 64 + Tn) slz2[s - 64] = g_logZ[b * Tn + (s - 64)];
    __syncthreads();
    if (s < Sn) skipf[s] = ((s & 1) && s >= 3 && ext[s] != ext[s - 2]) ? 1 : 0;

    const float* pp = preds + (long long)b * Tn * Cn;
    int ech = (s < Sn) ? ext[s] : 0;

    // init t = 0
    if (s < Sn) {
        float lz0 = slz2[0];
        bufA[s + 2] = (s < 2) ? (__ldg(pp + ech) - lz0) : NEGF;
    }
    __syncthreads();

    // depth-8 raw-logit prefetch ring (addresses known upfront)
    float pf[8];
#pragma unroll
    for (int q = 0; q < 8; q++) {
        int tq = 1 + q;
        pf[q] = (s < Sn && tq < Tn) ? __ldg(pp + (long long)tq * Cn + ech) : 0.f;
    }

    float* cur = bufA;
    float* nxt = bufB;
#pragma unroll 8
    for (int t = 1; t < Tn; t++) {
        float raw = pf[(t - 1) & 7];
        int tpre = t + 8;
        if (s < Sn && tpre < Tn)
            pf[(t - 1) & 7] = __ldg(pp + (long long)tpre * Cn + ech);
        if (s < Sn) {
            float a  = cur[s + 2];
            float a1 = cur[s + 1];
            float a2 = skipf[s] ? cur[s] : NEGF;
            float m  = fmaxf(a, fmaxf(a1, a2));
            float tot = m + logf(expf(a - m) + expf(a1 - m) + expf(a2 - m));
            float lp  = raw - slz2[t];
            nxt[s + 2] = (t < ilen) ? (tot + lp) : a;
        }
        __syncthreads();
        float* tmp = cur; cur = nxt; nxt = tmp;
    }

    if (s == 0) {
        int il = 2 * tlen;
        float ab = cur[il + 2];
        float ac = cur[il + 1];
        float nll = -lae(ab, ac);
        if (nll > 1e29f) nll = 0.f;             // zero_infinity
        g_nll[n] = nll;
    }
}

// ---------------- kernel 4: final scalar reduction ----------------
__global__ __launch_bounds__(Bn) void k_final(const int* __restrict__ length,
                                              const int* __restrict__ smooth_length,
                                              float* __restrict__ out)
{
    int b = threadIdx.x;                        // 0..127
    __shared__ float red[Bn];
    float lm = g_nll[b] / (float)length[b];
    float lc = 0.f;
#pragma unroll
    for (int k = 0; k < Kn; k++)
        lc += g_nll[Bn + b * Kn + k] / (float)smooth_length[b * Kn + k];
    lc *= (1.f / (float)Kn);
    float conf = g_conf[b];
    float omc = 1.f - conf;
    float r = TAIL_C + (1.f - TAIL_C) * omc * omc;
    red[b] = lm + ALPHA_C * r * lc;
    __syncthreads();
    for (int off = Bn / 2; off > 0; off >>= 1) {
        if (b < off) red[b] += red[b + off];
        __syncthreads();
    }
    if (b == 0) out[0] = red[0] / (float)Bn;
}

// ---------------- launch ----------------
extern "C" void kernel_launch(void* const* d_in, const int* in_sizes, int n_in,
                              void* d_out, int out_size) {
    const float* preds        = (const float*)d_in[0];
    const int*   text         = (const int*)d_in[1];
    const int*   preds_size   = (const int*)d_in[2];
    const int*   length       = (const int*)d_in[3];
    const int*   smooth_text  = (const int*)d_in[4];
    const int*   smooth_length= (const int*)d_in[5];
    float* out = (float*)d_out;

    k_rowstats<<<Bn * Tn, 256>>>(preds);
    k_gather  <<<Bn * Tn, NCAND>>>(preds);
    k_beam_ctc<<<Bn + NSEQ, 128>>>(preds, text, preds_size, length,
                                   smooth_text, smooth_length);
    k_final   <<<1, Bn>>>(length, smooth_length, out);
}

// round 3
// speedup vs baseline: 1.3633x; 1.3633x over previous
#include <cuda_runtime.h>
#include <math.h>
#include <float.h>

#define Bn 128
#define Tn 64
#define Cn 6625
#define Ln 25
#define Kn 6
#define Sn (2*Ln + 1)          // 51
#define NEGF (-1e30f)
#define ALPHA_C 0.1f
#define TAIL_C 0.01f
#define NSEQ (Bn + Bn*Kn)      // 896
#define NCAND 128
#define FULLM 0xffffffffu
#define RPT 26                 // 26*256 >= 6625

// ---------------- device scratch ----------------
__device__ float g_logZ[Bn*Tn];
__device__ float g_m1[Bn*Tn];
__device__ float g_m2[Bn*Tn];
__device__ int   g_i1[Bn*Tn];
__device__ int   g_i2[Bn*Tn];
__device__ float g_lpb0[Bn*Tn];
__device__ float g_tbl[Bn*Tn*NCAND];
__device__ float g_conf[Bn];
__device__ float g_nll[NSEQ];

// fast log-add-exp (MUFU)
__device__ __forceinline__ float lae(float a, float b) {
    float mx = fmaxf(a, b), mn = fminf(a, b);
    return mx + __logf(1.f + __expf(mn - mx));
}

// orderable float key (monotone float->uint32)
__device__ __forceinline__ unsigned int fkey(float v) {
    unsigned int b = __float_as_uint(v);
    return (b & 0x80000000u) ? ~b : (b | 0x80000000u);
}
__device__ __forceinline__ float fkey_inv(unsigned int k) {
    unsigned int b = (k & 0x80000000u) ? (k ^ 0x80000000u) : ~k;
    return __uint_as_float(b);
}

__device__ __forceinline__ void top2_merge(unsigned long long& a1, unsigned long long& a2,
                                           unsigned long long b1, unsigned long long b2) {
    unsigned long long n1 = (a1 > b1) ? a1 : b1;
    unsigned long long lo = (a1 > b1) ? b1 : a1;
    unsigned long long m2 = (a2 > b2) ? a2 : b2;
    a2 = (m2 > lo) ? m2 : lo;
    a1 = n1;
}

// ---------------- kernel 1: row stats (two-pass LSE + packed top-2) ----------------
__global__ __launch_bounds__(256) void k_rowstats(const float* __restrict__ preds) {
    int row = blockIdx.x;
    const float* p = preds + (long long)row * Cn;
    int tid = threadIdx.x;
    int lane = tid & 31, wid = tid >> 5;

    float r[RPT];
    float mx = -FLT_MAX;
    unsigned long long t1 = 0ull, t2 = 0ull;

#pragma unroll
    for (int k = 0; k < RPT; k++) {
        int c = tid + k * 256;
        bool ok = (c < Cn);
        float v = ok ? __ldg(p + c) : -FLT_MAX;
        r[k] = v;
        mx = fmaxf(mx, v);
        unsigned long long pk = (ok && c >= 1)
            ? (((unsigned long long)fkey(v) << 32) | (unsigned long long)(0xFFFFFFFFu - (unsigned)c))
            : 0ull;
        unsigned long long lo = (pk > t1) ? t1 : pk;
        t1 = (pk > t1) ? pk : t1;
        t2 = (lo > t2) ? lo : t2;
    }

#pragma unroll
    for (int off = 16; off > 0; off >>= 1) {
        mx = fmaxf(mx, __shfl_xor_sync(FULLM, mx, off));
        unsigned long long o1 = __shfl_xor_sync(FULLM, t1, off);
        unsigned long long o2 = __shfl_xor_sync(FULLM, t2, off);
        top2_merge(t1, t2, o1, o2);
    }

    __shared__ float s_mx[8];
    __shared__ unsigned long long s_t1[8], s_t2[8];
    __shared__ float s_bmx, s_sum;
    __shared__ float s_s[8];
    if (lane == 0) { s_mx[wid] = mx; s_t1[wid] = t1; s_t2[wid] = t2; }
    __syncthreads();

    if (wid == 0) {
        float m = (lane < 8) ? s_mx[lane] : -FLT_MAX;
        unsigned long long u1 = (lane < 8) ? s_t1[lane] : 0ull;
        unsigned long long u2 = (lane < 8) ? s_t2[lane] : 0ull;
#pragma unroll
        for (int off = 4; off > 0; off >>= 1) {
            m = fmaxf(m, __shfl_xor_sync(FULLM, m, off));
            unsigned long long o1 = __shfl_xor_sync(FULLM, u1, off);
            unsigned long long o2 = __shfl_xor_sync(FULLM, u2, off);
            top2_merge(u1, u2, o1, o2);
        }
        if (lane == 0) { s_bmx = m; s_t1[0] = u1; s_t2[0] = u2; }
    }
    __syncthreads();

    float bmx = s_bmx;
    float sum = 0.f;
#pragma unroll
    for (int k = 0; k < RPT; k++) sum += __expf(r[k] - bmx);

#pragma unroll
    for (int off = 16; off > 0; off >>= 1)
        sum += __shfl_xor_sync(FULLM, sum, off);
    if (lane == 0) s_s[wid] = sum;
    __syncthreads();
    if (wid == 0) {
        float sm = (lane < 8) ? s_s[lane] : 0.f;
#pragma unroll
        for (int off = 4; off > 0; off >>= 1) sm += __shfl_xor_sync(FULLM, sm, off);
        if (lane == 0) s_sum = sm;
    }
    __syncthreads();

    if (tid == 0) {
        float lz = bmx + __logf(s_sum);
        unsigned long long u1 = s_t1[0], u2 = s_t2[0];
        g_logZ[row] = lz;
        g_m1[row] = fkey_inv((unsigned int)(u1 >> 32));
        g_m2[row] = fkey_inv((unsigned int)(u2 >> 32));
        g_i1[row] = (int)(0xFFFFFFFFu - (unsigned int)(u1 & 0xFFFFFFFFull));
        g_i2[row] = (int)(0xFFFFFFFFu - (unsigned int)(u2 & 0xFFFFFFFFull));
        g_lpb0[row] = __ldg(p) - lz;
    }
}

// ---------------- kernel 2: gather beam candidate lp table ----------------
__global__ __launch_bounds__(NCAND) void k_gather(const float* __restrict__ preds) {
    int row = blockIdx.x;
    int j   = threadIdx.x;
    int b   = row / Tn;
    int ch  = (j < Tn) ? g_i1[b*Tn + j] : g_i2[b*Tn + (j - Tn)];
    g_tbl[(long long)row * NCAND + j] =
        __ldg(preds + (long long)row * Cn + ch) - g_logZ[row];
}

// ---------------- kernel 3: beam confidence + block-per-sequence CTC (R1-proven) ----
__global__ __launch_bounds__(128) void k_beam_ctc(
    const float* __restrict__ preds,
    const int* __restrict__ text,
    const int* __restrict__ preds_size,
    const int* __restrict__ length,
    const int* __restrict__ smooth_text,
    const int* __restrict__ smooth_length)
{
    int tid = threadIdx.x;

    if (blockIdx.x < Bn) {
        // ================= beam-1 prefix search =================
        int b = blockIdx.x;
        __shared__ float stbl[Tn * NCAND];      // 32KB
        __shared__ float sm1[Tn], sm2[Tn], slz[Tn], slpb[Tn];
        __shared__ int   si1[Tn], si2[Tn];

        const float* gt = g_tbl + (long long)b * Tn * NCAND;
#pragma unroll 8
        for (int idx = tid; idx < Tn * NCAND; idx += 128) stbl[idx] = gt[idx];
        if (tid < Tn) {
            int r = b * Tn + tid;
            sm1[tid] = g_m1[r]; sm2[tid] = g_m2[r];
            si1[tid] = g_i1[r]; si2[tid] = g_i2[r];
            slz[tid] = g_logZ[r]; slpb[tid] = g_lpb0[r];
        }
        __syncthreads();

        if (tid == 0) {
            float lpb = 0.f, lpnb = NEGF;
            int last = -1, lastj = 0;
            for (int t = 0; t < Tn; t++) {
                float lp_last = (last >= 0) ? stbl[t * NCAND + lastj] : NEGF;
                float tot    = lae(lpb, lpnb);
                float new_pb = tot + slpb[t];
                float rep    = (last >= 0) ? (lpnb + lp_last) : NEGF;
                float keep   = lae(new_pb, rep);
                float lpm1 = sm1[t] - slz[t];
                float lpm2 = sm2[t] - slz[t];
                float best_ext; int best_c, best_j;
                if (si1[t] != last) {
                    best_ext = tot + lpm1; best_c = si1[t]; best_j = t;
                } else {
                    float cA = lpb + lpm1;
                    float cB = tot + lpm2;
                    if (cA > cB || (cA == cB && last < si2[t])) {
                        best_ext = cA; best_c = last; best_j = t;
                    } else {
                        best_ext = cB; best_c = si2[t]; best_j = Tn + t;
                    }
                }
                bool take = best_ext > keep;
                lpb   = take ? NEGF     : new_pb;
                lpnb  = take ? best_ext : rep;
                last  = take ? best_c   : last;
                lastj = take ? best_j   : lastj;
            }
            float score = lae(lpb, lpnb);
            g_conf[b] = __expf(score / (float)Tn);
        }
        return;
    }

    // ================= CTC forward (R1 logic, fast intrinsics) =================
    int n = blockIdx.x - Bn;
    int b, tlen, ilen;
    const int* lab;
    if (n < Bn) {
        b = n; lab = text + n * Ln;
        tlen = length[n]; ilen = preds_size[n];
    } else {
        int m = n - Bn;
        b = m / Kn; lab = smooth_text + m * Ln;
        tlen = smooth_length[m]; ilen = Tn;
    }

    __shared__ int   ext[Sn];
    __shared__ int   skipf[Sn];
    __shared__ float bufA[Sn + 2], bufB[Sn + 2];
    __shared__ float slz2[Tn];

    int s = tid;
    if (s < Sn) ext[s] = (s & 1) ? lab[(s - 1) >> 1] : 0;
    if (s < 2) { bufA[s] = NEGF; bufB[s] = NEGF; }
    if (s >= 64 && s < 64 + Tn) slz2[s - 64] = g_logZ[b * Tn + (s - 64)];
    __syncthreads();
    if (s < Sn) skipf[s] = ((s & 1) && s >= 3 && ext[s] != ext[s - 2]) ? 1 : 0;

    const float* pp = preds + (long long)b * Tn * Cn;
    int ech = (s < Sn) ? ext[s] : 0;

    if (s < Sn) {
        float lz0 = slz2[0];
        bufA[s + 2] = (s < 2) ? (__ldg(pp + ech) - lz0) : NEGF;
    }
    __syncthreads();

    float pf[8];
#pragma unroll
    for (int q = 0; q < 8; q++) {
        int tq = 1 + q;
        pf[q] = (s < Sn && tq < Tn) ? __ldg(pp + (long long)tq * Cn + ech) : 0.f;
    }

    float* cur = bufA;
    float* nxt = bufB;
#pragma unroll 8
    for (int t = 1; t < Tn; t++) {
        float raw = pf[(t - 1) & 7];
        int tpre = t + 8;
        if (s < Sn && tpre < Tn)
            pf[(t - 1) & 7] = __ldg(pp + (long long)tpre * Cn + ech);
        if (s < Sn) {
            float a  = cur[s + 2];
            float a1 = cur[s + 1];
            float a2 = skipf[s] ? cur[s] : NEGF;
            float m  = fmaxf(a, fmaxf(a1, a2));
            float tot = m + __logf(__expf(a - m) + __expf(a1 - m) + __expf(a2 - m));
            float lp  = raw - slz2[t];
            nxt[s + 2] = (t < ilen) ? (tot + lp) : a;
        }
        __syncthreads();
        float* tmp = cur; cur = nxt; nxt = tmp;
    }

    if (s == 0) {
        int il = 2 * tlen;
        float ab = cur[il + 2];
        float ac = cur[il + 1];
        float nll = -lae(ab, ac);
        if (nll > 1e29f) nll = 0.f;
        g_nll[n] = nll;
    }
}

// ---------------- kernel 4: final scalar reduction ----------------
__global__ __launch_bounds__(Bn) void k_final(const int* __restrict__ length,
                                              const int* __restrict__ smooth_length,
                                              float* __restrict__ out)
{
    int b = threadIdx.x;
    __shared__ float red[Bn];
    float lm = g_nll[b] / (float)__ldg(length + b);
    float lc = 0.f;
#pragma unroll
    for (int k = 0; k < Kn; k++)
        lc += g_nll[Bn + b * Kn + k] / (float)__ldg(smooth_length + b * Kn + k);
    lc *= (1.f / (float)Kn);
    float conf = g_conf[b];
    float omc = 1.f - conf;
    float r = TAIL_C + (1.f - TAIL_C) * omc * omc;
    red[b] = lm + ALPHA_C * r * lc;
    __syncthreads();
    for (int off = Bn / 2; off > 0; off >>= 1) {
        if (b < off) red[b] += red[b + off];
        __syncthreads();
    }
    if (b == 0) out[0] = red[0] / (float)Bn;
}

// ---------------- launch ----------------
extern "C" void kernel_launch(void* const* d_in, const int* in_sizes, int n_in,
                              void* d_out, int out_size) {
    const float* preds         = (const float*)d_in[0];
    const int*   text          = (const int*)d_in[1];
    const int*   preds_size    = (const int*)d_in[2];
    const int*   length        = (const int*)d_in[3];
    const int*   smooth_text   = (const int*)d_in[4];
    const int*   smooth_length = (const int*)d_in[5];
    float* out = (float*)d_out;

    k_rowstats<<<Bn * Tn, 256>>>(preds);
    k_gather  <<<Bn * Tn, NCAND>>>(preds);
    k_beam_ctc<<<Bn + NSEQ, 128>>>(preds, text, preds_size, length,
                                   smooth_text, smooth_length);
    k_final   <<<1, Bn>>>(length, smooth_length, out);
}